// round 4
// baseline (speedup 1.0000x reference)
#include <cuda_runtime.h>
#include <math.h>

#define N_TOK 2304
#define CC    256
#define HEADS 8
#define DH    64
#define INNER 512
#define BATCH 4

// Scratch (device globals; no runtime allocation allowed)
__device__ float g_q[(size_t)BATCH*HEADS*DH*N_TOK]; // [b][h][d][n], already l2norm'd and *10
__device__ float g_k[(size_t)BATCH*HEADS*DH*N_TOK]; // [b][h][d][n], l2norm'd
__device__ float g_v[(size_t)BATCH*HEADS*N_TOK*DH]; // [b][h][n][d]
__device__ float g_o[(size_t)BATCH*INNER*N_TOK];    // [b][h][d][n] == [b][ci][n]

// ---------------------------------------------------------------------------
// Kernel A: QKV projection GEMM (per-batch [1536,256]x[256,2304]) with fused
// l2norm (+SCALE on Q) and transposed writes for Q/K.
// Block: 256 threads, tile 64(n) x 64(o=d), K-chunks of 16.
// ---------------------------------------------------------------------------
__global__ __launch_bounds__(256) void qkv_kernel(const float* __restrict__ x,
                                                  const float* __restrict__ wqkv) {
    const int nt = blockIdx.x;      // 0..35
    const int ot = blockIdx.y;      // 0..23  (part p = ot>>3, head h = ot&7)
    const int b  = blockIdx.z;      // 0..3
    const int n0 = nt * 64;
    const int o0 = ot * 64;
    const int p  = ot >> 3;
    const int h  = ot & 7;

    __shared__ float sX[16][64];   // sX[kk][nn]
    __shared__ float sW[16][68];   // sW[kk][oo], padded (272B rows, 16B aligned)
    __shared__ float sT[64][64];   // transpose staging

    const int t  = threadIdx.x;
    const int ty = t >> 4;
    const int tx = t & 15;

    float acc[4][4] = {};
    const float* xb = x + (size_t)b * CC * N_TOK;

    for (int c0 = 0; c0 < CC; c0 += 16) {
        {
            int kk = t >> 4, nn = (t & 15) * 4;
            *(float4*)&sX[kk][nn] =
                *(const float4*)&xb[(size_t)(c0 + kk) * N_TOK + n0 + nn];
        }
        {
            int oo = t >> 2, k4 = (t & 3) * 4;
            float4 w4 = *(const float4*)&wqkv[(size_t)(o0 + oo) * CC + c0 + k4];
            sW[k4 + 0][oo] = w4.x; sW[k4 + 1][oo] = w4.y;
            sW[k4 + 2][oo] = w4.z; sW[k4 + 3][oo] = w4.w;
        }
        __syncthreads();
#pragma unroll
        for (int kk = 0; kk < 16; kk++) {
            float4 a4 = *(float4*)&sX[kk][ty * 4];
            float4 b4 = *(float4*)&sW[kk][tx * 4];
            float a[4] = {a4.x, a4.y, a4.z, a4.w};
            float bb[4] = {b4.x, b4.y, b4.z, b4.w};
#pragma unroll
            for (int i = 0; i < 4; i++)
#pragma unroll
                for (int j = 0; j < 4; j++)
                    acc[i][j] += a[i] * bb[j];
        }
        __syncthreads();
    }

    const int bh = b * HEADS + h;

    if (p == 2) {
        // V: write [b][h][n][d] directly, coalesced
        float* dst = g_v + ((size_t)bh * N_TOK + n0) * DH;
#pragma unroll
        for (int i = 0; i < 4; i++) {
            float4 v4 = make_float4(acc[i][0], acc[i][1], acc[i][2], acc[i][3]);
            *(float4*)&dst[(size_t)(ty * 4 + i) * DH + tx * 4] = v4;
        }
    } else {
        // Q/K: l2-normalize each n-row (64 d values spread across tx group)
        float ssq[4];
#pragma unroll
        for (int i = 0; i < 4; i++)
            ssq[i] = acc[i][0] * acc[i][0] + acc[i][1] * acc[i][1] +
                     acc[i][2] * acc[i][2] + acc[i][3] * acc[i][3];
#pragma unroll
        for (int off = 8; off; off >>= 1)
#pragma unroll
            for (int i = 0; i < 4; i++)
                ssq[i] += __shfl_xor_sync(0xffffffffu, ssq[i], off);

        const float sf = (p == 0) ? 10.0f : 1.0f;   // fold SCALE into Q
#pragma unroll
        for (int i = 0; i < 4; i++) {
            float inv = sf / fmaxf(sqrtf(ssq[i]), 1e-12f);
            acc[i][0] *= inv; acc[i][1] *= inv;
            acc[i][2] *= inv; acc[i][3] *= inv;
        }
        // stage [n][d] then write transposed to [d][n]
#pragma unroll
        for (int i = 0; i < 4; i++)
            *(float4*)&sT[ty * 4 + i][tx * 4] =
                make_float4(acc[i][0], acc[i][1], acc[i][2], acc[i][3]);
        __syncthreads();

        float* dst = (p == 0 ? g_q : g_k) + (size_t)bh * DH * N_TOK;
        int d = t >> 2, c4 = (t & 3) * 16;
#pragma unroll
        for (int k = 0; k < 4; k++) {
            int nn = c4 + k * 4;
            float4 v4 = make_float4(sT[nn][d], sT[nn + 1][d],
                                    sT[nn + 2][d], sT[nn + 3][d]);
            *(float4*)&dst[(size_t)d * N_TOK + n0 + nn] = v4;
        }
    }
}

// ---------------------------------------------------------------------------
// Kernel B: flash attention, fp32. One block = (b, h, 64-row q tile).
// Q,K in [d][n] layout (conflict-free shared tiles), V in [n][d].
// Online softmax; P staged via shared for the PV GEMM.
// ---------------------------------------------------------------------------
extern __shared__ float attn_smem[];
__global__ __launch_bounds__(256, 2) void attn_kernel() {
    float* sQ = attn_smem;            // [64][64]  (Q^T: [d][n])
    float* sK = attn_smem + 4096;     // [64][64]  (K^T: [d][n])
    float* sV = attn_smem + 8192;     // [64][64]  ([n][d])
    float* sP = attn_smem + 12288;    // [64][64]  ([qr][kc])

    const int qt = blockIdx.x;        // 0..35
    const int h  = blockIdx.y;
    const int b  = blockIdx.z;
    const int bh = b * HEADS + h;
    const int n0 = qt * 64;

    const float* Qd = g_q + (size_t)bh * DH * N_TOK;
    const float* Kd = g_k + (size_t)bh * DH * N_TOK;
    const float* Vp = g_v + (size_t)bh * N_TOK * DH;
    float*       Od = g_o + (size_t)bh * DH * N_TOK;

    const int t  = threadIdx.x;
    const int ty = t >> 4;
    const int tx = t & 15;
    const int lr = t >> 2;            // loader row 0..63
    const int lc = (t & 3) * 16;      // loader col chunk

#pragma unroll
    for (int k = 0; k < 4; k++)
        *(float4*)&sQ[lr * 64 + lc + k * 4] =
            *(const float4*)&Qd[(size_t)lr * N_TOK + n0 + lc + k * 4];

    float o[4][4] = {};
    float m[4] = {-1e30f, -1e30f, -1e30f, -1e30f};
    float l[4] = {0.f, 0.f, 0.f, 0.f};

    for (int j0 = 0; j0 < N_TOK; j0 += 64) {
        __syncthreads();   // prev iter done with sK/sV/sP (also publishes sQ on iter 0)
#pragma unroll
        for (int k = 0; k < 4; k++)
            *(float4*)&sK[lr * 64 + lc + k * 4] =
                *(const float4*)&Kd[(size_t)lr * N_TOK + j0 + lc + k * 4];
#pragma unroll
        for (int k = 0; k < 4; k++)
            *(float4*)&sV[lr * 64 + lc + k * 4] =
                *(const float4*)&Vp[(size_t)(j0 + lr) * DH + lc + k * 4];
        __syncthreads();

        // S = (10*q_norm) . k_norm  over d
        float s[4][4] = {};
#pragma unroll 8
        for (int dd = 0; dd < 64; dd++) {
            float4 a4 = *(float4*)&sQ[dd * 64 + ty * 4];
            float4 b4 = *(float4*)&sK[dd * 64 + tx * 4];
            float a[4] = {a4.x, a4.y, a4.z, a4.w};
            float bb[4] = {b4.x, b4.y, b4.z, b4.w};
#pragma unroll
            for (int i = 0; i < 4; i++)
#pragma unroll
                for (int j = 0; j < 4; j++)
                    s[i][j] += a[i] * bb[j];
        }

        // online softmax (row state replicated across the 16-lane tx group)
        float mx[4];
#pragma unroll
        for (int i = 0; i < 4; i++)
            mx[i] = fmaxf(fmaxf(s[i][0], s[i][1]), fmaxf(s[i][2], s[i][3]));
#pragma unroll
        for (int off = 8; off; off >>= 1)
#pragma unroll
            for (int i = 0; i < 4; i++)
                mx[i] = fmaxf(mx[i], __shfl_xor_sync(0xffffffffu, mx[i], off));

        float corr[4];
#pragma unroll
        for (int i = 0; i < 4; i++) {
            float nm = fmaxf(m[i], mx[i]);
            corr[i] = __expf(m[i] - nm);
            m[i] = nm;
        }
#pragma unroll
        for (int i = 0; i < 4; i++)
#pragma unroll
            for (int j = 0; j < 4; j++)
                s[i][j] = __expf(s[i][j] - m[i]);

        float rs[4];
#pragma unroll
        for (int i = 0; i < 4; i++)
            rs[i] = s[i][0] + s[i][1] + s[i][2] + s[i][3];
#pragma unroll
        for (int off = 8; off; off >>= 1)
#pragma unroll
            for (int i = 0; i < 4; i++)
                rs[i] += __shfl_xor_sync(0xffffffffu, rs[i], off);
#pragma unroll
        for (int i = 0; i < 4; i++) {
            l[i] = l[i] * corr[i] + rs[i];
            o[i][0] *= corr[i]; o[i][1] *= corr[i];
            o[i][2] *= corr[i]; o[i][3] *= corr[i];
        }

#pragma unroll
        for (int i = 0; i < 4; i++)
            *(float4*)&sP[(ty * 4 + i) * 64 + tx * 4] =
                make_float4(s[i][0], s[i][1], s[i][2], s[i][3]);
        __syncthreads();

        // O += P @ V
#pragma unroll 8
        for (int jj = 0; jj < 64; jj++) {
            float4 b4 = *(float4*)&sV[jj * 64 + tx * 4];
#pragma unroll
            for (int i = 0; i < 4; i++) {
                float a = sP[(ty * 4 + i) * 64 + jj];
                o[i][0] += a * b4.x; o[i][1] += a * b4.y;
                o[i][2] += a * b4.z; o[i][3] += a * b4.w;
            }
        }
    }

#pragma unroll
    for (int i = 0; i < 4; i++) {
        float inv = 1.0f / l[i];
        o[i][0] *= inv; o[i][1] *= inv; o[i][2] *= inv; o[i][3] *= inv;
    }

    // write O transposed to [d][n] (stage through sP)
    __syncthreads();
#pragma unroll
    for (int i = 0; i < 4; i++)
        *(float4*)&sP[(ty * 4 + i) * 64 + tx * 4] =
            make_float4(o[i][0], o[i][1], o[i][2], o[i][3]);
    __syncthreads();

    int d = t >> 2, c4 = (t & 3) * 16;
#pragma unroll
    for (int k = 0; k < 4; k++) {
        int nn = c4 + k * 4;
        float4 v4 = make_float4(sP[nn * 64 + d], sP[(nn + 1) * 64 + d],
                                sP[(nn + 2) * 64 + d], sP[(nn + 3) * 64 + d]);
        *(float4*)&Od[(size_t)d * N_TOK + n0 + nn] = v4;
    }
}

// ---------------------------------------------------------------------------
// Kernel C: output projection  out[b,o,n] = sum_ci wout[o,ci]*g_o[b,ci,n] + bias
// ---------------------------------------------------------------------------
__global__ __launch_bounds__(256) void out_kernel(const float* __restrict__ wout,
                                                  const float* __restrict__ bias,
                                                  float* __restrict__ out) {
    const int nt = blockIdx.x;   // 0..35
    const int ot = blockIdx.y;   // 0..3
    const int b  = blockIdx.z;   // 0..3
    const int n0 = nt * 64;
    const int o0 = ot * 64;

    __shared__ float sG[16][64];  // sG[kk][nn]
    __shared__ float sW[16][68];  // sW[kk][oo]

    const int t  = threadIdx.x;
    const int ty = t >> 4;
    const int tx = t & 15;

    float acc[4][4] = {};
    const float* gb = g_o + (size_t)b * INNER * N_TOK;

    for (int c0 = 0; c0 < INNER; c0 += 16) {
        {
            int kk = t >> 4, nn = (t & 15) * 4;
            *(float4*)&sG[kk][nn] =
                *(const float4*)&gb[(size_t)(c0 + kk) * N_TOK + n0 + nn];
        }
        {
            int oo = t >> 2, k4 = (t & 3) * 4;
            float4 w4 = *(const float4*)&wout[(size_t)(o0 + oo) * INNER + c0 + k4];
            sW[k4 + 0][oo] = w4.x; sW[k4 + 1][oo] = w4.y;
            sW[k4 + 2][oo] = w4.z; sW[k4 + 3][oo] = w4.w;
        }
        __syncthreads();
#pragma unroll
        for (int kk = 0; kk < 16; kk++) {
            float4 a4 = *(float4*)&sW[kk][ty * 4];   // rows = o
            float4 b4 = *(float4*)&sG[kk][tx * 4];   // cols = n
            float a[4] = {a4.x, a4.y, a4.z, a4.w};
            float bb[4] = {b4.x, b4.y, b4.z, b4.w};
#pragma unroll
            for (int i = 0; i < 4; i++)
#pragma unroll
                for (int j = 0; j < 4; j++)
                    acc[i][j] += a[i] * bb[j];
        }
        __syncthreads();
    }

    float* ob = out + ((size_t)b * CC + o0) * N_TOK;
#pragma unroll
    for (int i = 0; i < 4; i++) {
        float bi = bias[o0 + ty * 4 + i];
        float4 v4 = make_float4(acc[i][0] + bi, acc[i][1] + bi,
                                acc[i][2] + bi, acc[i][3] + bi);
        *(float4*)&ob[(size_t)(ty * 4 + i) * N_TOK + n0 + tx * 4] = v4;
    }
}

// ---------------------------------------------------------------------------
extern "C" void kernel_launch(void* const* d_in, const int* in_sizes, int n_in,
                              void* d_out, int out_size) {
    const float* x    = (const float*)d_in[0];
    const float* wqkv = (const float*)d_in[1];
    const float* wout = (const float*)d_in[2];
    const float* bout = (const float*)d_in[3];
    float* out = (float*)d_out;

    (void)in_sizes; (void)n_in; (void)out_size;

    // 64KB dynamic smem for the attention kernel (4x 64x64 fp32 tiles)
    cudaFuncSetAttribute(attn_kernel, cudaFuncAttributeMaxDynamicSharedMemorySize,
                         65536);

    qkv_kernel<<<dim3(36, 24, 4), 256>>>(x, wqkv);
    attn_kernel<<<dim3(36, 8, 4), 256, 65536>>>();
    out_kernel<<<dim3(36, 4, 4), 256>>>(wout, bout, out);
}

// round 8
// speedup vs baseline: 2.4694x; 2.4694x over previous
#include <cuda_runtime.h>
#include <math.h>
#include <stdint.h>

#define N_TOK 2304
#define CC    256
#define HEADS 8
#define DH    64
#define INNER 512
#define BATCH 4

// Scratch (device globals; no runtime allocation allowed)
__device__ float g_q[(size_t)BATCH*HEADS*N_TOK*DH]; // [b][h][n][d]  l2norm'd * 10, tf32-rounded
__device__ float g_k[(size_t)BATCH*HEADS*N_TOK*DH]; // [b][h][n][d]  l2norm'd, tf32-rounded
__device__ float g_v[(size_t)BATCH*HEADS*N_TOK*DH]; // [b][h][n][d]  tf32-rounded
__device__ float g_o[(size_t)BATCH*INNER*N_TOK];    // [b][ci][n]

__device__ __forceinline__ float tf32r(float x) {
    uint32_t u; asm("cvt.rna.tf32.f32 %0, %1;" : "=r"(u) : "f"(x));
    return __uint_as_float(u);
}
__device__ __forceinline__ uint32_t tf32bits(float x) {
    uint32_t u; asm("cvt.rna.tf32.f32 %0, %1;" : "=r"(u) : "f"(x));
    return u;
}

// Warp-level tf32 MMA: D(16x8) += A(16x8) * B(8x8), row.col
__device__ __forceinline__ void mma_tf32(float c[4],
                                         uint32_t a0, uint32_t a1, uint32_t a2, uint32_t a3,
                                         uint32_t b0, uint32_t b1) {
    asm volatile(
        "mma.sync.aligned.m16n8k8.row.col.f32.tf32.tf32.f32 "
        "{%0,%1,%2,%3}, {%4,%5,%6,%7}, {%8,%9}, {%0,%1,%2,%3};"
        : "+f"(c[0]), "+f"(c[1]), "+f"(c[2]), "+f"(c[3])
        : "r"(a0), "r"(a1), "r"(a2), "r"(a3), "r"(b0), "r"(b1));
}

// ---------------------------------------------------------------------------
// Kernel A: QKV projection GEMM with fused l2norm (+SCALE on Q), tf32 rounding.
// Q,K,V all written [b][h][n][d].
// ---------------------------------------------------------------------------
__global__ __launch_bounds__(256) void qkv_kernel(const float* __restrict__ x,
                                                  const float* __restrict__ wqkv) {
    const int nt = blockIdx.x;
    const int ot = blockIdx.y;
    const int b  = blockIdx.z;
    const int n0 = nt * 64;
    const int o0 = ot * 64;
    const int p  = ot >> 3;
    const int h  = ot & 7;

    __shared__ float sX[16][64];
    __shared__ float sW[16][68];

    const int t  = threadIdx.x;
    const int ty = t >> 4;   // n sub-index
    const int tx = t & 15;   // d sub-index

    float acc[4][4] = {};
    const float* xb = x + (size_t)b * CC * N_TOK;

    for (int c0 = 0; c0 < CC; c0 += 16) {
        {
            int kk = t >> 4, nn = (t & 15) * 4;
            *(float4*)&sX[kk][nn] = *(const float4*)&xb[(size_t)(c0 + kk) * N_TOK + n0 + nn];
        }
        {
            int oo = t >> 2, k4 = (t & 3) * 4;
            float4 w4 = *(const float4*)&wqkv[(size_t)(o0 + oo) * CC + c0 + k4];
            sW[k4 + 0][oo] = w4.x; sW[k4 + 1][oo] = w4.y;
            sW[k4 + 2][oo] = w4.z; sW[k4 + 3][oo] = w4.w;
        }
        __syncthreads();
#pragma unroll
        for (int kk = 0; kk < 16; kk++) {
            float4 a4 = *(float4*)&sX[kk][ty * 4];
            float4 b4 = *(float4*)&sW[kk][tx * 4];
            float a[4] = {a4.x, a4.y, a4.z, a4.w};
            float bb[4] = {b4.x, b4.y, b4.z, b4.w};
#pragma unroll
            for (int i = 0; i < 4; i++)
#pragma unroll
                for (int j = 0; j < 4; j++)
                    acc[i][j] += a[i] * bb[j];
        }
        __syncthreads();
    }

    const int bh = b * HEADS + h;

    if (p == 2) {
        // V: write [n][d] directly, tf32-rounded, coalesced
        float* dst = g_v + ((size_t)bh * N_TOK + n0) * DH;
#pragma unroll
        for (int i = 0; i < 4; i++) {
            float4 v4 = make_float4(tf32r(acc[i][0]), tf32r(acc[i][1]),
                                    tf32r(acc[i][2]), tf32r(acc[i][3]));
            *(float4*)&dst[(size_t)(ty * 4 + i) * DH + tx * 4] = v4;
        }
    } else {
        // Q/K: l2-normalize rows (d spread across 16-lane tx group)
        float ssq[4];
#pragma unroll
        for (int i = 0; i < 4; i++)
            ssq[i] = acc[i][0] * acc[i][0] + acc[i][1] * acc[i][1] +
                     acc[i][2] * acc[i][2] + acc[i][3] * acc[i][3];
#pragma unroll
        for (int off = 8; off; off >>= 1)
#pragma unroll
            for (int i = 0; i < 4; i++)
                ssq[i] += __shfl_xor_sync(0xffffffffu, ssq[i], off);

        const float sf = (p == 0) ? 10.0f : 1.0f;   // fold SCALE into Q
        float* dst = (p == 0 ? g_q : g_k) + ((size_t)bh * N_TOK + n0) * DH;
#pragma unroll
        for (int i = 0; i < 4; i++) {
            float inv = sf / fmaxf(sqrtf(ssq[i]), 1e-12f);
            float4 v4 = make_float4(tf32r(acc[i][0] * inv), tf32r(acc[i][1] * inv),
                                    tf32r(acc[i][2] * inv), tf32r(acc[i][3] * inv));
            *(float4*)&dst[(size_t)(ty * 4 + i) * DH + tx * 4] = v4;
        }
    }
}

// ---------------------------------------------------------------------------
// Kernel B: tf32 mma.sync flash attention.
// CTA = 128 q rows, 8 warps x 16 rows. kv-tiles of 64.
// Fixed softmax max SCALE=10 (s = 10*cos <= 10): no online rescaling;
// O accumulates in registers across all kv-tiles; one final 1/l normalize.
// ---------------------------------------------------------------------------
#define PADK 68
#define PADV 72
#define PADP 68
#define SK_OFF 0
#define SV_OFF (64 * PADK)
#define SP_OFF (64 * PADK + 64 * PADV)
#define ATT_SMEM_FLOATS (64 * PADK + 64 * PADV + 128 * PADP)
#define NKT (N_TOK / 64)

extern __shared__ float att_smem[];
__global__ __launch_bounds__(256, 2) void attn_mma_kernel() {
    float* sK = att_smem + SK_OFF;   // [64][PADK]  K tile [kv][d]
    float* sV = att_smem + SV_OFF;   // [64][PADV]  V tile [kv][d]
    float* sP = att_smem + SP_OFF;   // [128][PADP] Q staging / P / O staging

    const int t    = threadIdx.x;
    const int lane = t & 31;
    const int wid  = t >> 5;
    const int qt   = blockIdx.x;
    const int h    = blockIdx.y;
    const int b    = blockIdx.z;
    const int bh   = b * HEADS + h;
    const int n0   = qt * 128;

    const int r  = lane >> 2;   // group id 0..7
    const int cl = lane & 3;    // thread in group
    const int qrow = wid * 16 + r;

    // ---- Stage Q tile (128 x 64) into sP, then pick up A-fragments ----
    {
        int row = t >> 1, cc = (t & 1) * 32;
        const float* Qg = g_q + ((size_t)bh * N_TOK + n0 + row) * DH + cc;
#pragma unroll
        for (int c = 0; c < 8; c++)
            *(float4*)&sP[row * PADP + cc + c * 4] = *(const float4*)&Qg[c * 4];
    }
    __syncthreads();

    uint32_t qa[8][4];
#pragma unroll
    for (int k = 0; k < 8; k++) {
        qa[k][0] = __float_as_uint(sP[qrow * PADP + k * 8 + cl]);
        qa[k][1] = __float_as_uint(sP[(qrow + 8) * PADP + k * 8 + cl]);
        qa[k][2] = __float_as_uint(sP[qrow * PADP + k * 8 + cl + 4]);
        qa[k][3] = __float_as_uint(sP[(qrow + 8) * PADP + k * 8 + cl + 4]);
    }

    float o[8][4] = {};
    float l0 = 0.0f, l1 = 0.0f;

    const int rowKV = t >> 2;
    const int ccKV  = (t & 3) * 16;

    for (int it = 0; it < NKT; it++) {
        __syncthreads();   // previous iteration done with sK/sV (and sP Q-staging on it=0)
        {
            const float* Kg = g_k + ((size_t)bh * N_TOK + it * 64 + rowKV) * DH + ccKV;
            const float* Vg = g_v + ((size_t)bh * N_TOK + it * 64 + rowKV) * DH + ccKV;
#pragma unroll
            for (int c = 0; c < 4; c++) {
                *(float4*)&sK[rowKV * PADK + ccKV + c * 4] = *(const float4*)&Kg[c * 4];
                *(float4*)&sV[rowKV * PADV + ccKV + c * 4] = *(const float4*)&Vg[c * 4];
            }
        }
        __syncthreads();

        // ---- S = Q . K^T : per warp 16 x 64 ----
        float s[8][4];
#pragma unroll
        for (int n = 0; n < 8; n++) {
            s[n][0] = s[n][1] = s[n][2] = s[n][3] = 0.0f;
#pragma unroll
            for (int k = 0; k < 8; k++) {
                uint32_t b0 = __float_as_uint(sK[(n * 8 + r) * PADK + k * 8 + cl]);
                uint32_t b1 = __float_as_uint(sK[(n * 8 + r) * PADK + k * 8 + cl + 4]);
                mma_tf32(s[n], qa[k][0], qa[k][1], qa[k][2], qa[k][3], b0, b1);
            }
        }

        // ---- p = exp(s - 10); accumulate row sums; store P (tf32) to sP ----
#pragma unroll
        for (int n = 0; n < 8; n++) {
            float p0 = __expf(s[n][0] - 10.0f);
            float p1 = __expf(s[n][1] - 10.0f);
            float p2 = __expf(s[n][2] - 10.0f);
            float p3 = __expf(s[n][3] - 10.0f);
            l0 += p0 + p1;
            l1 += p2 + p3;
            float2 lo = make_float2(tf32r(p0), tf32r(p1));
            float2 hi = make_float2(tf32r(p2), tf32r(p3));
            *(float2*)&sP[qrow * PADP + n * 8 + 2 * cl] = lo;
            *(float2*)&sP[(qrow + 8) * PADP + n * 8 + 2 * cl] = hi;
        }
        // no sync needed: each warp reads back only its own 16 rows of sP

        // ---- O += P . V : per warp 16 x 64 over kv=64 ----
#pragma unroll
        for (int k = 0; k < 8; k++) {
            uint32_t a0 = __float_as_uint(sP[qrow * PADP + k * 8 + cl]);
            uint32_t a1 = __float_as_uint(sP[(qrow + 8) * PADP + k * 8 + cl]);
            uint32_t a2 = __float_as_uint(sP[qrow * PADP + k * 8 + cl + 4]);
            uint32_t a3 = __float_as_uint(sP[(qrow + 8) * PADP + k * 8 + cl + 4]);
#pragma unroll
            for (int n = 0; n < 8; n++) {
                uint32_t b0 = __float_as_uint(sV[(k * 8 + cl) * PADV + n * 8 + r]);
                uint32_t b1 = __float_as_uint(sV[(k * 8 + cl + 4) * PADV + n * 8 + r]);
                mma_tf32(o[n], a0, a1, a2, a3, b0, b1);
            }
        }
    }

    // ---- finalize row sums (quad reduce) and normalize ----
    l0 += __shfl_xor_sync(0xffffffffu, l0, 1);
    l0 += __shfl_xor_sync(0xffffffffu, l0, 2);
    l1 += __shfl_xor_sync(0xffffffffu, l1, 1);
    l1 += __shfl_xor_sync(0xffffffffu, l1, 2);
    const float inv0 = 1.0f / l0;
    const float inv1 = 1.0f / l1;

    __syncthreads();   // everyone done with sK/sV/sP reads
#pragma unroll
    for (int n = 0; n < 8; n++) {
        *(float2*)&sP[qrow * PADP + n * 8 + 2 * cl] =
            make_float2(o[n][0] * inv0, o[n][1] * inv0);
        *(float2*)&sP[(qrow + 8) * PADP + n * 8 + 2 * cl] =
            make_float2(o[n][2] * inv1, o[n][3] * inv1);
    }
    __syncthreads();

    // transposed write: g_o[bh*DH + d][n0 + q]
    {
        const int d  = t >> 2;
        const int qc = (t & 3) * 32;
        float* Ob = g_o + ((size_t)bh * DH + d) * N_TOK + n0 + qc;
#pragma unroll
        for (int i = 0; i < 8; i++) {
            int q = qc + i * 4;
            float4 v4 = make_float4(sP[(q + 0) * PADP + d], sP[(q + 1) * PADP + d],
                                    sP[(q + 2) * PADP + d], sP[(q + 3) * PADP + d]);
            *(float4*)&Ob[i * 4 - qc + qc] = v4;   // = Ob[i*4]
        }
    }
}

// ---------------------------------------------------------------------------
// Kernel C: output projection  out[b,o,n] = sum_ci wout[o,ci]*g_o[b,ci,n] + bias
// ---------------------------------------------------------------------------
__global__ __launch_bounds__(256) void out_kernel(const float* __restrict__ wout,
                                                  const float* __restrict__ bias,
                                                  float* __restrict__ out) {
    const int nt = blockIdx.x;
    const int ot = blockIdx.y;
    const int b  = blockIdx.z;
    const int n0 = nt * 64;
    const int o0 = ot * 64;

    __shared__ float sG[16][64];
    __shared__ float sW[16][68];

    const int t  = threadIdx.x;
    const int ty = t >> 4;
    const int tx = t & 15;

    float acc[4][4] = {};
    const float* gb = g_o + (size_t)b * INNER * N_TOK;

    for (int c0 = 0; c0 < INNER; c0 += 16) {
        {
            int kk = t >> 4, nn = (t & 15) * 4;
            *(float4*)&sG[kk][nn] = *(const float4*)&gb[(size_t)(c0 + kk) * N_TOK + n0 + nn];
        }
        {
            int oo = t >> 2, k4 = (t & 3) * 4;
            float4 w4 = *(const float4*)&wout[(size_t)(o0 + oo) * INNER + c0 + k4];
            sW[k4 + 0][oo] = w4.x; sW[k4 + 1][oo] = w4.y;
            sW[k4 + 2][oo] = w4.z; sW[k4 + 3][oo] = w4.w;
        }
        __syncthreads();
#pragma unroll
        for (int kk = 0; kk < 16; kk++) {
            float4 a4 = *(float4*)&sW[kk][ty * 4];
            float4 b4 = *(float4*)&sG[kk][tx * 4];
            float a[4] = {a4.x, a4.y, a4.z, a4.w};
            float bb[4] = {b4.x, b4.y, b4.z, b4.w};
#pragma unroll
            for (int i = 0; i < 4; i++)
#pragma unroll
                for (int j = 0; j < 4; j++)
                    acc[i][j] += a[i] * bb[j];
        }
        __syncthreads();
    }

    float* ob = out + ((size_t)b * CC + o0) * N_TOK;
#pragma unroll
    for (int i = 0; i < 4; i++) {
        float bi = bias[o0 + ty * 4 + i];
        float4 v4 = make_float4(acc[i][0] + bi, acc[i][1] + bi,
                                acc[i][2] + bi, acc[i][3] + bi);
        *(float4*)&ob[(size_t)(ty * 4 + i) * N_TOK + n0 + tx * 4] = v4;
    }
}

// ---------------------------------------------------------------------------
extern "C" void kernel_launch(void* const* d_in, const int* in_sizes, int n_in,
                              void* d_out, int out_size) {
    const float* x    = (const float*)d_in[0];
    const float* wqkv = (const float*)d_in[1];
    const float* wout = (const float*)d_in[2];
    const float* bout = (const float*)d_in[3];
    float* out = (float*)d_out;

    (void)in_sizes; (void)n_in; (void)out_size;

    cudaFuncSetAttribute(attn_mma_kernel, cudaFuncAttributeMaxDynamicSharedMemorySize,
                         ATT_SMEM_FLOATS * sizeof(float));

    qkv_kernel<<<dim3(36, 24, 4), 256>>>(x, wqkv);
    attn_mma_kernel<<<dim3(18, 8, 4), 256, ATT_SMEM_FLOATS * sizeof(float)>>>();
    out_kernel<<<dim3(36, 4, 4), 256>>>(wout, bout, out);
}